// round 7
// baseline (speedup 1.0000x reference)
#include <cuda_runtime.h>
#include <cstdint>

// Segment offsets scratch: offsets[n] = first edge index whose segment id >= n.
#define MAX_SEGMENTS 131072
__device__ int g_offsets[MAX_SEGMENTS + 1];

// ---------------------------------------------------------------------------
// Kernel 1: streaming offsets builder (index is SORTED): thread e writes
// offsets[n] = e for n in (index[e-1], index[e]]; thread E-1 fills the tail.
// Dtype robustness: JAX x64-off silently downcasts int64->int32; if truly
// int64 (values < 2^31) the low word sits at position 2m. Detect via 3
// trailing odd words (all zero iff int64 high halves).
// ---------------------------------------------------------------------------
__global__ void build_offsets_kernel(const unsigned int* __restrict__ w,
                                     int E, int N) {
    int e = blockIdx.x * blockDim.x + threadIdx.x;
    if (e >= E) return;

    int j = E - 1;
    if ((j & 1) == 0) j -= 1;
    unsigned int acc = 0;
    for (int k = 0; k < 3 && j - 2 * k >= 1; ++k)
        acc |= __ldg(&w[j - 2 * k]);
    const int shift = (acc == 0) ? 1 : 0;    // word index = m << shift

    int cur  = (int)__ldg(&w[((unsigned)e) << shift]);
    int prev = (e == 0) ? -1 : (int)__ldg(&w[((unsigned)(e - 1)) << shift]);

    for (int n = prev + 1; n <= cur; ++n)
        g_offsets[n] = e;

    if (e == E - 1) {
        for (int n = cur + 1; n <= N; ++n)
            g_offsets[n] = E;
    }
}

// ---------------------------------------------------------------------------
// Kernel 2: ONE WARP PER SEGMENT (the R3 scheduling — empirically best; all
// warp-serialized multi-segment variants measured slower). Inner loop is a
// batch-8 predicated loader: with Poisson(6.4) segment lengths, ~80% of
// segments finish in a single batch of <=8 independent back-to-back LDG.128s
// (front-batched MLP ~6.4 vs 2 for unroll-2+tail), then a tree reduce, one
// multiply, one streaming store, retire. Lane l owns float4 column 4l
// (D=128 -> one column per lane). Empty segments write zeros (output is
// poisoned 0xAA and must be fully overwritten).
// ---------------------------------------------------------------------------
__global__ void __launch_bounds__(256)
segment_mean_kernel(const float* __restrict__ x,
                    float* __restrict__ out,
                    int D, int N) {
    int gwarp = (blockIdx.x * blockDim.x + threadIdx.x) >> 5;
    int lane  = threadIdx.x & 31;
    if (gwarp >= N) return;

    int s = g_offsets[gwarp];
    int e = g_offsets[gwarp + 1];
    int cnt = e - s;
    float inv = (cnt > 0) ? (1.0f / (float)cnt) : 0.0f;

    for (int c = lane * 4; c < D; c += 32 * 4) {
        float4 a[8];
        #pragma unroll
        for (int i = 0; i < 8; ++i) a[i] = make_float4(0.f, 0.f, 0.f, 0.f);

        const float* p = x + (size_t)s * D + c;
        for (int r = s; r < e; r += 8, p += 8 * D) {
            int m = e - r;   // rows remaining (>=1)
            #pragma unroll
            for (int i = 0; i < 8; ++i) {
                if (i < m) {
                    float4 v = __ldcs(reinterpret_cast<const float4*>(p + (size_t)i * D));
                    a[i].x += v.x; a[i].y += v.y; a[i].z += v.z; a[i].w += v.w;
                }
            }
        }

        // Tree reduction of the 8 accumulators.
        #pragma unroll
        for (int st = 4; st > 0; st >>= 1) {
            #pragma unroll
            for (int i = 0; i < 4; ++i) {
                if (i < st) {
                    a[i].x += a[i + st].x; a[i].y += a[i + st].y;
                    a[i].z += a[i + st].z; a[i].w += a[i + st].w;
                }
            }
        }

        float4 res;
        res.x = a[0].x * inv;
        res.y = a[0].y * inv;
        res.z = a[0].z * inv;
        res.w = a[0].w * inv;
        __stcs(reinterpret_cast<float4*>(out + (size_t)gwarp * D + c), res);
    }
}

// ---------------------------------------------------------------------------
// Launch
// Inputs (metadata order): d_in[0] = x (float32, E*D), d_in[1] = index (E,
// int32 or int64 — detected on device), d_in[2] = dim_size (unused).
// ---------------------------------------------------------------------------
extern "C" void kernel_launch(void* const* d_in, const int* in_sizes, int n_in,
                              void* d_out, int out_size) {
    const float*        x   = (const float*)d_in[0];
    const unsigned int* idx = (const unsigned int*)d_in[1];
    float*              out = (float*)d_out;

    int E = in_sizes[1];          // 640000
    int D = in_sizes[0] / E;      // 128
    int N = out_size / D;         // 100000

    // Kernel 1: streaming segment boundaries (E threads).
    {
        int threads = 256;
        int blocks = (E + threads - 1) / threads;
        build_offsets_kernel<<<blocks, threads>>>(idx, E, N);
    }

    // Kernel 2: one warp per segment, 8 warps per 256-thread block.
    {
        int threads = 256;
        int warps_per_block = threads / 32;
        int blocks = (N + warps_per_block - 1) / warps_per_block;
        segment_mean_kernel<<<blocks, threads>>>(x, out, D, N);
    }
}

// round 8
// speedup vs baseline: 1.2255x; 1.2255x over previous
#include <cuda_runtime.h>
#include <cstdint>

// Segment offsets scratch: offsets[n] = first edge index whose segment id >= n.
#define MAX_SEGMENTS 131072
__device__ int g_offsets[MAX_SEGMENTS + 1];

#define BLOCK_THREADS 128   // 4 warps/CTA: shrinks CTA-retirement max-of-k imbalance

// ---------------------------------------------------------------------------
// Kernel 1: streaming offsets builder (index is SORTED): thread e writes
// offsets[n] = e for n in (index[e-1], index[e]]; thread E-1 fills the tail.
// Dtype robustness: JAX x64-off silently downcasts int64->int32; if truly
// int64 (values < 2^31) the low word sits at position 2m. Detect via 3
// trailing odd words (all zero iff int64 high halves).
// ---------------------------------------------------------------------------
__global__ void build_offsets_kernel(const unsigned int* __restrict__ w,
                                     int E, int N) {
    int e = blockIdx.x * blockDim.x + threadIdx.x;
    if (e >= E) return;

    int j = E - 1;
    if ((j & 1) == 0) j -= 1;
    unsigned int acc = 0;
    for (int k = 0; k < 3 && j - 2 * k >= 1; ++k)
        acc |= __ldg(&w[j - 2 * k]);
    const int shift = (acc == 0) ? 1 : 0;    // word index = m << shift

    int cur  = (int)__ldg(&w[((unsigned)e) << shift]);
    int prev = (e == 0) ? -1 : (int)__ldg(&w[((unsigned)(e - 1)) << shift]);

    for (int n = prev + 1; n <= cur; ++n)
        g_offsets[n] = e;

    if (e == E - 1) {
        for (int n = cur + 1; n <= N; ++n)
            g_offsets[n] = E;
    }
}

// ---------------------------------------------------------------------------
// Kernel 2: ONE WARP PER SEGMENT — the empirically best scheduling (R3:
// 61us main, 57% occ; all multi-segment-per-warp and batch-8 variants
// measured slower). Unroll-2 dual-accumulator inner loop keeps regs ~38
// (R7 showed 8 accumulators -> 72 regs -> 30% occ -> 84us). Block=128
// (4 warps) shrinks the CTA-retirement max-of-k Poisson imbalance vs 8.
// Lane l owns float4 column 4l (D=128 -> one column per lane). __ldcs
// read-once x stream, __stcs write-once output. Empty segments write zeros
// (output is poisoned 0xAA and must be fully overwritten).
// ---------------------------------------------------------------------------
__global__ void __launch_bounds__(BLOCK_THREADS)
segment_mean_kernel(const float* __restrict__ x,
                    float* __restrict__ out,
                    int D, int N) {
    int gwarp = (blockIdx.x * blockDim.x + threadIdx.x) >> 5;
    int lane  = threadIdx.x & 31;
    if (gwarp >= N) return;

    int s = g_offsets[gwarp];
    int e = g_offsets[gwarp + 1];
    int cnt = e - s;
    float inv = (cnt > 0) ? (1.0f / (float)cnt) : 0.0f;

    for (int c = lane * 4; c < D; c += 32 * 4) {
        float4 a0 = make_float4(0.f, 0.f, 0.f, 0.f);
        float4 a1 = make_float4(0.f, 0.f, 0.f, 0.f);
        const float* p = x + (size_t)s * D + c;
        int r = s;
        for (; r + 2 <= e; r += 2, p += 2 * D) {
            float4 v0 = __ldcs(reinterpret_cast<const float4*>(p));
            float4 v1 = __ldcs(reinterpret_cast<const float4*>(p + D));
            a0.x += v0.x; a0.y += v0.y; a0.z += v0.z; a0.w += v0.w;
            a1.x += v1.x; a1.y += v1.y; a1.z += v1.z; a1.w += v1.w;
        }
        if (r < e) {
            float4 v0 = __ldcs(reinterpret_cast<const float4*>(p));
            a0.x += v0.x; a0.y += v0.y; a0.z += v0.z; a0.w += v0.w;
        }
        float4 res;
        res.x = (a0.x + a1.x) * inv;
        res.y = (a0.y + a1.y) * inv;
        res.z = (a0.z + a1.z) * inv;
        res.w = (a0.w + a1.w) * inv;
        __stcs(reinterpret_cast<float4*>(out + (size_t)gwarp * D + c), res);
    }
}

// ---------------------------------------------------------------------------
// Launch
// Inputs (metadata order): d_in[0] = x (float32, E*D), d_in[1] = index (E,
// int32 or int64 — detected on device), d_in[2] = dim_size (unused).
// ---------------------------------------------------------------------------
extern "C" void kernel_launch(void* const* d_in, const int* in_sizes, int n_in,
                              void* d_out, int out_size) {
    const float*        x   = (const float*)d_in[0];
    const unsigned int* idx = (const unsigned int*)d_in[1];
    float*              out = (float*)d_out;

    int E = in_sizes[1];          // 640000
    int D = in_sizes[0] / E;      // 128
    int N = out_size / D;         // 100000

    // Kernel 1: streaming segment boundaries (E threads).
    {
        int threads = 256;
        int blocks = (E + threads - 1) / threads;
        build_offsets_kernel<<<blocks, threads>>>(idx, E, N);
    }

    // Kernel 2: one warp per segment, 4 warps per 128-thread block.
    {
        int warps_per_block = BLOCK_THREADS / 32;
        int blocks = (N + warps_per_block - 1) / warps_per_block;
        segment_mean_kernel<<<blocks, BLOCK_THREADS>>>(x, out, D, N);
    }
}

// round 9
// speedup vs baseline: 1.2511x; 1.0209x over previous
#include <cuda_runtime.h>
#include <cstdint>

// Segment offsets scratch: offsets[n] = first edge index whose segment id >= n.
#define MAX_SEGMENTS 131072
__device__ int g_offsets[MAX_SEGMENTS + 1];

#define BLOCK_THREADS 64   // 2 warps/CTA: minimal CTA-retirement max-of-k imbalance

// ---------------------------------------------------------------------------
// Kernel 1: streaming offsets builder (index is SORTED): thread e writes
// offsets[n] = e for n in (index[e-1], index[e]]; thread E-1 fills the tail.
// Dtype robustness: JAX x64-off silently downcasts int64->int32; if truly
// int64 (values < 2^31) the low word sits at position 2m. Detect via 3
// trailing odd words (all zero iff int64 high halves).
// ---------------------------------------------------------------------------
__global__ void build_offsets_kernel(const unsigned int* __restrict__ w,
                                     int E, int N) {
    int e = blockIdx.x * blockDim.x + threadIdx.x;
    if (e >= E) return;

    int j = E - 1;
    if ((j & 1) == 0) j -= 1;
    unsigned int acc = 0;
    for (int k = 0; k < 3 && j - 2 * k >= 1; ++k)
        acc |= __ldg(&w[j - 2 * k]);
    const int shift = (acc == 0) ? 1 : 0;    // word index = m << shift

    int cur  = (int)__ldg(&w[((unsigned)e) << shift]);
    int prev = (e == 0) ? -1 : (int)__ldg(&w[((unsigned)(e - 1)) << shift]);

    for (int n = prev + 1; n <= cur; ++n)
        g_offsets[n] = e;

    if (e == E - 1) {
        for (int n = cur + 1; n <= N; ++n)
            g_offsets[n] = E;
    }
}

// ---------------------------------------------------------------------------
// Kernel 2: ONE WARP PER SEGMENT — the empirically best scheduling. Unroll-2
// dual-accumulator keeps regs ~38 (R7: 8 accs -> 72 regs -> occ collapse).
// Block=64 (2 warps/CTA): retirement waits on max-of-2 Poisson instead of
// max-of-4 (R8 showed 256->128 raised occ 57->60% and won; this continues
// the measured gradient). Lane l owns float4 column 4l (D=128 -> exactly one
// column per lane). __ldcs read-once x stream, __stcs write-once output.
// Empty segments write zeros (output poisoned 0xAA, must be overwritten).
// ---------------------------------------------------------------------------
__global__ void __launch_bounds__(BLOCK_THREADS)
segment_mean_kernel(const float* __restrict__ x,
                    float* __restrict__ out,
                    int D, int N) {
    int gwarp = (blockIdx.x * blockDim.x + threadIdx.x) >> 5;
    int lane  = threadIdx.x & 31;
    if (gwarp >= N) return;

    int s = __ldg(&g_offsets[gwarp]);
    int e = __ldg(&g_offsets[gwarp + 1]);
    int cnt = e - s;
    float inv = (cnt > 0) ? (1.0f / (float)cnt) : 0.0f;

    for (int c = lane * 4; c < D; c += 32 * 4) {
        float4 a0 = make_float4(0.f, 0.f, 0.f, 0.f);
        float4 a1 = make_float4(0.f, 0.f, 0.f, 0.f);
        const float* p = x + (size_t)s * D + c;
        int r = s;
        for (; r + 2 <= e; r += 2, p += 2 * D) {
            float4 v0 = __ldcs(reinterpret_cast<const float4*>(p));
            float4 v1 = __ldcs(reinterpret_cast<const float4*>(p + D));
            a0.x += v0.x; a0.y += v0.y; a0.z += v0.z; a0.w += v0.w;
            a1.x += v1.x; a1.y += v1.y; a1.z += v1.z; a1.w += v1.w;
        }
        if (r < e) {
            float4 v0 = __ldcs(reinterpret_cast<const float4*>(p));
            a0.x += v0.x; a0.y += v0.y; a0.z += v0.z; a0.w += v0.w;
        }
        float4 res;
        res.x = (a0.x + a1.x) * inv;
        res.y = (a0.y + a1.y) * inv;
        res.z = (a0.z + a1.z) * inv;
        res.w = (a0.w + a1.w) * inv;
        __stcs(reinterpret_cast<float4*>(out + (size_t)gwarp * D + c), res);
    }
}

// ---------------------------------------------------------------------------
// Launch
// Inputs (metadata order): d_in[0] = x (float32, E*D), d_in[1] = index (E,
// int32 or int64 — detected on device), d_in[2] = dim_size (unused).
// ---------------------------------------------------------------------------
extern "C" void kernel_launch(void* const* d_in, const int* in_sizes, int n_in,
                              void* d_out, int out_size) {
    const float*        x   = (const float*)d_in[0];
    const unsigned int* idx = (const unsigned int*)d_in[1];
    float*              out = (float*)d_out;

    int E = in_sizes[1];          // 640000
    int D = in_sizes[0] / E;      // 128
    int N = out_size / D;         // 100000

    // Kernel 1: streaming segment boundaries (E threads).
    {
        int threads = 256;
        int blocks = (E + threads - 1) / threads;
        build_offsets_kernel<<<blocks, threads>>>(idx, E, N);
    }

    // Kernel 2: one warp per segment, 2 warps per 64-thread block.
    {
        int warps_per_block = BLOCK_THREADS / 32;
        int blocks = (N + warps_per_block - 1) / warps_per_block;
        segment_mean_kernel<<<blocks, BLOCK_THREADS>>>(x, out, D, N);
    }
}

// round 10
// speedup vs baseline: 1.3126x; 1.0491x over previous
#include <cuda_runtime.h>
#include <cstdint>

// Segment offsets scratch: offsets[n] = first edge index whose segment id >= n.
#define MAX_SEGMENTS 131072
__device__ int g_offsets[MAX_SEGMENTS + 1];

#define BLOCK_THREADS 64   // 2 warps/CTA: minimal CTA-retirement max-of-k imbalance
#define EDGES_PER_THREAD 4

// ---------------------------------------------------------------------------
// Kernel 1: streaming offsets builder (index is SORTED): for each adjacent
// pair, boundaries n in (index[e-1], index[e]] get offsets[n] = e. Each
// thread handles EDGES_PER_THREAD consecutive edges (fewer threads, less
// per-thread fixed overhead; loads stay coalesced). Last edge fills the tail.
// Dtype robustness: JAX x64-off silently downcasts int64->int32; if truly
// int64 (values < 2^31) the low word sits at position 2m. Detect via 3
// trailing odd words (all zero iff int64 high halves).
// ---------------------------------------------------------------------------
__global__ void build_offsets_kernel(const unsigned int* __restrict__ w,
                                     int E, int N) {
    int t = blockIdx.x * blockDim.x + threadIdx.x;
    int e0 = t * EDGES_PER_THREAD;
    if (e0 >= E) return;

    int j = E - 1;
    if ((j & 1) == 0) j -= 1;
    unsigned int acc = 0;
    for (int k = 0; k < 3 && j - 2 * k >= 1; ++k)
        acc |= __ldg(&w[j - 2 * k]);
    const int shift = (acc == 0) ? 1 : 0;    // word index = m << shift

    int prev = (e0 == 0) ? -1 : (int)__ldg(&w[((unsigned)(e0 - 1)) << shift]);

    #pragma unroll
    for (int k = 0; k < EDGES_PER_THREAD; ++k) {
        int e = e0 + k;
        if (e >= E) break;
        int cur = (int)__ldg(&w[((unsigned)e) << shift]);
        for (int n = prev + 1; n <= cur; ++n)
            g_offsets[n] = e;
        if (e == E - 1) {
            for (int n = cur + 1; n <= N; ++n)
                g_offsets[n] = E;
        }
        prev = cur;
    }
}

// ---------------------------------------------------------------------------
// Kernel 2: ONE WARP PER SEGMENT — the empirically best scheduling (R3/R8/R9
// gradient). Row loop unrolled x4 with FOUR transient load registers but only
// TWO accumulators: front-batched MLP=4 (outstanding bytes per warp doubled
// vs R9) while long-lived register state stays small (R7 showed 8 live
// accumulators -> 72 regs -> occupancy collapse). Block=64. Lane l owns
// float4 column 4l (D=128 -> one column per lane). __ldcs read-once x
// stream, __stcs write-once output. Empty segments write zeros (output is
// poisoned 0xAA and must be fully overwritten).
// ---------------------------------------------------------------------------
__global__ void __launch_bounds__(BLOCK_THREADS)
segment_mean_kernel(const float* __restrict__ x,
                    float* __restrict__ out,
                    int D, int N) {
    int gwarp = (blockIdx.x * blockDim.x + threadIdx.x) >> 5;
    int lane  = threadIdx.x & 31;
    if (gwarp >= N) return;

    int s = __ldg(&g_offsets[gwarp]);
    int e = __ldg(&g_offsets[gwarp + 1]);
    int cnt = e - s;
    float inv = (cnt > 0) ? (1.0f / (float)cnt) : 0.0f;

    for (int c = lane * 4; c < D; c += 32 * 4) {
        float4 a0 = make_float4(0.f, 0.f, 0.f, 0.f);
        float4 a1 = make_float4(0.f, 0.f, 0.f, 0.f);
        const float* p = x + (size_t)s * D + c;
        int r = s;
        for (; r + 4 <= e; r += 4, p += 4 * D) {
            float4 v0 = __ldcs(reinterpret_cast<const float4*>(p));
            float4 v1 = __ldcs(reinterpret_cast<const float4*>(p + D));
            float4 v2 = __ldcs(reinterpret_cast<const float4*>(p + 2 * D));
            float4 v3 = __ldcs(reinterpret_cast<const float4*>(p + 3 * D));
            a0.x += v0.x; a0.y += v0.y; a0.z += v0.z; a0.w += v0.w;
            a1.x += v1.x; a1.y += v1.y; a1.z += v1.z; a1.w += v1.w;
            a0.x += v2.x; a0.y += v2.y; a0.z += v2.z; a0.w += v2.w;
            a1.x += v3.x; a1.y += v3.y; a1.z += v3.z; a1.w += v3.w;
        }
        if (r + 2 <= e) {
            float4 v0 = __ldcs(reinterpret_cast<const float4*>(p));
            float4 v1 = __ldcs(reinterpret_cast<const float4*>(p + D));
            a0.x += v0.x; a0.y += v0.y; a0.z += v0.z; a0.w += v0.w;
            a1.x += v1.x; a1.y += v1.y; a1.z += v1.z; a1.w += v1.w;
            r += 2; p += 2 * D;
        }
        if (r < e) {
            float4 v0 = __ldcs(reinterpret_cast<const float4*>(p));
            a0.x += v0.x; a0.y += v0.y; a0.z += v0.z; a0.w += v0.w;
        }
        float4 res;
        res.x = (a0.x + a1.x) * inv;
        res.y = (a0.y + a1.y) * inv;
        res.z = (a0.z + a1.z) * inv;
        res.w = (a0.w + a1.w) * inv;
        __stcs(reinterpret_cast<float4*>(out + (size_t)gwarp * D + c), res);
    }
}

// ---------------------------------------------------------------------------
// Launch
// Inputs (metadata order): d_in[0] = x (float32, E*D), d_in[1] = index (E,
// int32 or int64 — detected on device), d_in[2] = dim_size (unused).
// ---------------------------------------------------------------------------
extern "C" void kernel_launch(void* const* d_in, const int* in_sizes, int n_in,
                              void* d_out, int out_size) {
    const float*        x   = (const float*)d_in[0];
    const unsigned int* idx = (const unsigned int*)d_in[1];
    float*              out = (float*)d_out;

    int E = in_sizes[1];          // 640000
    int D = in_sizes[0] / E;      // 128
    int N = out_size / D;         // 100000

    // Kernel 1: streaming segment boundaries, 4 edges per thread.
    {
        int threads = 256;
        long long work = ((long long)E + EDGES_PER_THREAD - 1) / EDGES_PER_THREAD;
        int blocks = (int)((work + threads - 1) / threads);
        build_offsets_kernel<<<blocks, threads>>>(idx, E, N);
    }

    // Kernel 2: one warp per segment, 2 warps per 64-thread block.
    {
        int warps_per_block = BLOCK_THREADS / 32;
        int blocks = (N + warps_per_block - 1) / warps_per_block;
        segment_mean_kernel<<<blocks, BLOCK_THREADS>>>(x, out, D, N);
    }
}